// round 3
// baseline (speedup 1.0000x reference)
#include <cuda_runtime.h>

#define BB  2
#define SS  2048
#define DD  1024
#define HH  16
#define DHH 64

// Scratch (allocation-free rule: __device__ globals)
__device__ float g_QH[BB*HH*SS*DHH];   // [B,H,S,DH]
__device__ float g_KH[BB*HH*SS*DHH];
__device__ float g_VH[BB*HH*SS*DHH];
__device__ float g_O [BB*SS*DD];       // [B,S,D] (head-merged) for final GEMM

// ---------------------------------------------------------------------------
// Projection: C[M=B*S, N=D] = X[M,K=D] @ W[N,K]^T, scattered to [B,H,S,DH]
// 128x128 tile, BK=8, 256 threads, 8x8 microtile
// ---------------------------------------------------------------------------
__global__ __launch_bounds__(256) void proj_kernel(
    const float* __restrict__ X, const float* __restrict__ W, int which)
{
    __shared__ float As[8][128];
    __shared__ float Bs[8][128];
    const int tid = threadIdx.x;
    const int m0 = blockIdx.y * 128;
    const int n0 = blockIdx.x * 128;
    const int lr = tid >> 1;             // 0..127
    const int lc = (tid & 1) << 2;       // 0 or 4
    const float* Ap = X + (size_t)(m0 + lr) * DD + lc;
    const float* Bp = W + (size_t)(n0 + lr) * DD + lc;
    const int tx = tid & 15, ty = tid >> 4;

    float acc[8][8];
    #pragma unroll
    for (int i = 0; i < 8; i++)
        #pragma unroll
        for (int j = 0; j < 8; j++) acc[i][j] = 0.f;

    for (int k0 = 0; k0 < DD; k0 += 8) {
        float4 a = *(const float4*)(Ap + k0);
        float4 b = *(const float4*)(Bp + k0);
        As[lc+0][lr] = a.x; As[lc+1][lr] = a.y; As[lc+2][lr] = a.z; As[lc+3][lr] = a.w;
        Bs[lc+0][lr] = b.x; Bs[lc+1][lr] = b.y; Bs[lc+2][lr] = b.z; Bs[lc+3][lr] = b.w;
        __syncthreads();
        #pragma unroll
        for (int k = 0; k < 8; k++) {
            float ar[8], br[8];
            #pragma unroll
            for (int i = 0; i < 8; i++) ar[i] = As[k][ty*8 + i];
            #pragma unroll
            for (int j = 0; j < 8; j++) br[j] = Bs[k][tx*8 + j];
            #pragma unroll
            for (int i = 0; i < 8; i++)
                #pragma unroll
                for (int j = 0; j < 8; j++)
                    acc[i][j] += ar[i] * br[j];
        }
        __syncthreads();
    }

    float* dst = (which == 0) ? g_QH : (which == 1) ? g_KH : g_VH;
    #pragma unroll
    for (int i = 0; i < 8; i++) {
        int m = m0 + ty*8 + i;
        int b = m >> 11;            // m / S
        int s = m & (SS - 1);
        #pragma unroll
        for (int j = 0; j < 8; j++) {
            int n = n0 + tx*8 + j;
            int h = n >> 6;         // n / DH
            int d = n & 63;
            dst[(((size_t)(b*HH + h)*SS + s) << 6) + d] = acc[i][j];
        }
    }
}

// ---------------------------------------------------------------------------
// Scores: per (b,h): S_mat = (QH @ KH^T) * 1/8, masked; written into attn region
// ---------------------------------------------------------------------------
__global__ __launch_bounds__(256) void scores_kernel(
    const int* __restrict__ mask, float* __restrict__ attn)
{
    __shared__ float As[8][128];
    __shared__ float Bs[8][128];
    const int tid = threadIdx.x;
    const int bh = blockIdx.z;
    const int m0 = blockIdx.y * 128;
    const int n0 = blockIdx.x * 128;
    const float* A  = g_QH + (size_t)bh * SS * DHH;
    const float* Bm = g_KH + (size_t)bh * SS * DHH;
    const int lr = tid >> 1;
    const int lc = (tid & 1) << 2;
    const float* Ap = A  + (size_t)(m0 + lr) * DHH + lc;
    const float* Bp = Bm + (size_t)(n0 + lr) * DHH + lc;
    const int tx = tid & 15, ty = tid >> 4;

    float acc[8][8];
    #pragma unroll
    for (int i = 0; i < 8; i++)
        #pragma unroll
        for (int j = 0; j < 8; j++) acc[i][j] = 0.f;

    for (int k0 = 0; k0 < DHH; k0 += 8) {
        float4 a = *(const float4*)(Ap + k0);
        float4 b = *(const float4*)(Bp + k0);
        As[lc+0][lr] = a.x; As[lc+1][lr] = a.y; As[lc+2][lr] = a.z; As[lc+3][lr] = a.w;
        Bs[lc+0][lr] = b.x; Bs[lc+1][lr] = b.y; Bs[lc+2][lr] = b.z; Bs[lc+3][lr] = b.w;
        __syncthreads();
        #pragma unroll
        for (int k = 0; k < 8; k++) {
            float ar[8], br[8];
            #pragma unroll
            for (int i = 0; i < 8; i++) ar[i] = As[k][ty*8 + i];
            #pragma unroll
            for (int j = 0; j < 8; j++) br[j] = Bs[k][tx*8 + j];
            #pragma unroll
            for (int i = 0; i < 8; i++)
                #pragma unroll
                for (int j = 0; j < 8; j++)
                    acc[i][j] += ar[i] * br[j];
        }
        __syncthreads();
    }

    float* Cp = attn + (size_t)bh * SS * SS;
    #pragma unroll
    for (int i = 0; i < 8; i++) {
        int m = m0 + ty*8 + i;
        const int* mrow = mask + (size_t)m * SS;
        float* crow = Cp + (size_t)m * SS;
        #pragma unroll
        for (int j = 0; j < 8; j++) {
            int n = n0 + tx*8 + j;
            float val = acc[i][j] * 0.125f;
            if (mrow[n] == 0) val = -1e34f;
            crow[n] = val;
        }
    }
}

// ---------------------------------------------------------------------------
// Row softmax in place: one block (256 thr) per row of 2048
// ---------------------------------------------------------------------------
__global__ __launch_bounds__(256) void softmax_kernel(float* __restrict__ attn)
{
    __shared__ float red[8];
    const size_t row = blockIdx.x;
    float* p = attn + row * SS;
    const int tid = threadIdx.x;

    float4 v0 = ((float4*)p)[tid];
    float4 v1 = ((float4*)p)[tid + 256];

    float m = fmaxf(fmaxf(fmaxf(v0.x, v0.y), fmaxf(v0.z, v0.w)),
                    fmaxf(fmaxf(v1.x, v1.y), fmaxf(v1.z, v1.w)));
    #pragma unroll
    for (int o = 16; o; o >>= 1) m = fmaxf(m, __shfl_xor_sync(0xffffffffu, m, o));
    if ((tid & 31) == 0) red[tid >> 5] = m;
    __syncthreads();
    if (tid == 0) {
        float mm = red[0];
        #pragma unroll
        for (int w = 1; w < 8; w++) mm = fmaxf(mm, red[w]);
        red[0] = mm;
    }
    __syncthreads();
    m = red[0];
    __syncthreads();

    v0.x = __expf(v0.x - m); v0.y = __expf(v0.y - m);
    v0.z = __expf(v0.z - m); v0.w = __expf(v0.w - m);
    v1.x = __expf(v1.x - m); v1.y = __expf(v1.y - m);
    v1.z = __expf(v1.z - m); v1.w = __expf(v1.w - m);

    float s = (v0.x + v0.y + v0.z + v0.w) + (v1.x + v1.y + v1.z + v1.w);
    #pragma unroll
    for (int o = 16; o; o >>= 1) s += __shfl_xor_sync(0xffffffffu, s, o);
    if ((tid & 31) == 0) red[tid >> 5] = s;
    __syncthreads();
    if (tid == 0) {
        float ss = red[0];
        #pragma unroll
        for (int w = 1; w < 8; w++) ss += red[w];
        red[0] = ss;
    }
    __syncthreads();
    s = red[0];

    float inv = 1.0f / s;
    v0.x *= inv; v0.y *= inv; v0.z *= inv; v0.w *= inv;
    v1.x *= inv; v1.y *= inv; v1.z *= inv; v1.w *= inv;
    ((float4*)p)[tid]       = v0;
    ((float4*)p)[tid + 256] = v1;
}

// ---------------------------------------------------------------------------
// PV: per (b,h): O_tile[S,64] = attn[S,S] @ VH[S,64]; O stored [B,S,D]
// BM=128, BN=64, BK=16, 256 threads, 8x4 microtile
// ---------------------------------------------------------------------------
__global__ __launch_bounds__(256) void pv_kernel(const float* __restrict__ attn)
{
    __shared__ float Ps[16][128];
    __shared__ float Vs[16][64];
    const int tid = threadIdx.x;
    const int bh = blockIdx.z;
    const int b  = bh >> 4;
    const int h  = bh & 15;
    const int m0 = blockIdx.x * 128;
    const float* P = attn + (size_t)bh * SS * SS;
    const float* V = g_VH + (size_t)bh * SS * DHH;
    const int tx = tid & 15, ty = tid >> 4;

    float acc[8][4];
    #pragma unroll
    for (int i = 0; i < 8; i++)
        #pragma unroll
        for (int j = 0; j < 4; j++) acc[i][j] = 0.f;

    const int vr = tid >> 4;            // 0..15
    const int vc = (tid & 15) << 2;     // 0..60

    for (int k0 = 0; k0 < SS; k0 += 16) {
        #pragma unroll
        for (int i = 0; i < 2; i++) {
            int lin = tid + i * 256;
            int r = lin >> 2;
            int c = (lin & 3) << 2;
            float4 pv = *(const float4*)(P + (size_t)(m0 + r) * SS + k0 + c);
            Ps[c+0][r] = pv.x; Ps[c+1][r] = pv.y; Ps[c+2][r] = pv.z; Ps[c+3][r] = pv.w;
        }
        {
            float4 vv = *(const float4*)(V + (size_t)(k0 + vr) * DHH + vc);
            *(float4*)&Vs[vr][vc] = vv;
        }
        __syncthreads();
        #pragma unroll
        for (int k = 0; k < 16; k++) {
            float pr[8], vrg[4];
            #pragma unroll
            for (int i = 0; i < 8; i++) pr[i] = Ps[k][ty*8 + i];
            #pragma unroll
            for (int j = 0; j < 4; j++) vrg[j] = Vs[k][tx*4 + j];
            #pragma unroll
            for (int i = 0; i < 8; i++)
                #pragma unroll
                for (int j = 0; j < 4; j++)
                    acc[i][j] += pr[i] * vrg[j];
        }
        __syncthreads();
    }

    #pragma unroll
    for (int i = 0; i < 8; i++) {
        int sm = m0 + ty*8 + i;
        float* orow = g_O + (size_t)(b*SS + sm) * DD + h*DHH + tx*4;
        *(float4*)orow = *(float4*)&acc[i][0];
    }
}

// ---------------------------------------------------------------------------
// Output: out[M=B*S, N=D] = g_O[M,K=D] @ Wo[N,K]^T, plain row-major
// ---------------------------------------------------------------------------
__global__ __launch_bounds__(256) void out_kernel(
    const float* __restrict__ Wo, float* __restrict__ out)
{
    __shared__ float As[8][128];
    __shared__ float Bs[8][128];
    const int tid = threadIdx.x;
    const int m0 = blockIdx.y * 128;
    const int n0 = blockIdx.x * 128;
    const int lr = tid >> 1;
    const int lc = (tid & 1) << 2;
    const float* Ap = g_O + (size_t)(m0 + lr) * DD + lc;
    const float* Bp = Wo  + (size_t)(n0 + lr) * DD + lc;
    const int tx = tid & 15, ty = tid >> 4;

    float acc[8][8];
    #pragma unroll
    for (int i = 0; i < 8; i++)
        #pragma unroll
        for (int j = 0; j < 8; j++) acc[i][j] = 0.f;

    for (int k0 = 0; k0 < DD; k0 += 8) {
        float4 a = *(const float4*)(Ap + k0);
        float4 b = *(const float4*)(Bp + k0);
        As[lc+0][lr] = a.x; As[lc+1][lr] = a.y; As[lc+2][lr] = a.z; As[lc+3][lr] = a.w;
        Bs[lc+0][lr] = b.x; Bs[lc+1][lr] = b.y; Bs[lc+2][lr] = b.z; Bs[lc+3][lr] = b.w;
        __syncthreads();
        #pragma unroll
        for (int k = 0; k < 8; k++) {
            float ar[8], br[8];
            #pragma unroll
            for (int i = 0; i < 8; i++) ar[i] = As[k][ty*8 + i];
            #pragma unroll
            for (int j = 0; j < 8; j++) br[j] = Bs[k][tx*8 + j];
            #pragma unroll
            for (int i = 0; i < 8; i++)
                #pragma unroll
                for (int j = 0; j < 8; j++)
                    acc[i][j] += ar[i] * br[j];
        }
        __syncthreads();
    }

    #pragma unroll
    for (int i = 0; i < 8; i++) {
        int m = m0 + ty*8 + i;
        float* crow = out + (size_t)m * DD + n0 + tx*8;
        *(float4*)(crow)     = *(float4*)&acc[i][0];
        *(float4*)(crow + 4) = *(float4*)&acc[i][4];
    }
}

// ---------------------------------------------------------------------------
extern "C" void kernel_launch(void* const* d_in, const int* in_sizes, int n_in,
                              void* d_out, int out_size)
{
    const float* q    = (const float*)d_in[0];
    const float* k    = (const float*)d_in[1];
    const float* v    = (const float*)d_in[2];
    const int*   mask = (const int*)  d_in[3];
    const float* Wq   = (const float*)d_in[4];
    const float* Wk   = (const float*)d_in[5];
    const float* Wv   = (const float*)d_in[6];
    const float* Wo   = (const float*)d_in[7];

    float* out  = (float*)d_out;
    float* attn = out + (size_t)BB * SS * DD;   // out first, then attn

    dim3 blk(256);
    dim3 gp(DD / 128, (BB * SS) / 128);         // 8 x 32
    proj_kernel<<<gp, blk>>>(q, Wq, 0);
    proj_kernel<<<gp, blk>>>(k, Wk, 1);
    proj_kernel<<<gp, blk>>>(v, Wv, 2);

    dim3 gs(SS / 128, SS / 128, BB * HH);       // 16 x 16 x 32
    scores_kernel<<<gs, blk>>>(mask, attn);

    softmax_kernel<<<BB * HH * SS, blk>>>(attn);

    pv_kernel<<<dim3(SS / 128, 1, BB * HH), blk>>>(attn);

    out_kernel<<<gp, blk>>>(Wo, out);
}

// round 5
// speedup vs baseline: 1.4954x; 1.4954x over previous
#include <cuda_runtime.h>
#include <cstdint>

#define BB  2
#define SS  2048
#define DD  1024
#define HH  16
#define DHH 64

// Scratch (allocation-free rule: __device__ globals)
__device__ float g_QH[BB*HH*SS*DHH];   // [B,H,S,DH]
__device__ float g_KH[BB*HH*SS*DHH];   // [B,H,S,DH]
__device__ float g_VT[BB*HH*DHH*SS];   // [B,H,DH,S]  (transposed V for NT PV gemm)
__device__ float g_O [BB*SS*DD];       // [B,S,D]

// ---------------------------------------------------------------------------
// tf32 mma.sync helpers
// ---------------------------------------------------------------------------
__device__ __forceinline__ unsigned f2tf(float f) {
    unsigned u;
    asm("cvt.rna.tf32.f32 %0, %1;" : "=r"(u) : "f"(f));
    return u;
}

__device__ __forceinline__ void mma8(float c[4],
                                     unsigned a0, unsigned a1, unsigned a2, unsigned a3,
                                     unsigned b0, unsigned b1) {
    asm("mma.sync.aligned.m16n8k8.row.col.f32.tf32.tf32.f32 "
        "{%0,%1,%2,%3},{%4,%5,%6,%7},{%8,%9},{%0,%1,%2,%3};"
        : "+f"(c[0]), "+f"(c[1]), "+f"(c[2]), "+f"(c[3])
        : "r"(a0), "r"(a1), "r"(a2), "r"(a3), "r"(b0), "r"(b1));
}

// Load a 128-row x 32-col tile (converted to tf32) into smem [128][36]
__device__ __forceinline__ void load128(const float* __restrict__ g, int ld,
                                        int row0, int k0, unsigned (*S)[36], int tid) {
    int r = tid >> 1;
    int c = (tid & 1) << 4;
    const float* p = g + (size_t)(row0 + r) * ld + k0 + c;
    #pragma unroll
    for (int i = 0; i < 4; i++) {
        float4 v = *(const float4*)(p + 4*i);
        uint4 u;
        u.x = f2tf(v.x); u.y = f2tf(v.y); u.z = f2tf(v.z); u.w = f2tf(v.w);
        *(uint4*)&S[r][c + 4*i] = u;
    }
}

// Load a 64-row x 32-col tile into smem [64][36]
__device__ __forceinline__ void load64(const float* __restrict__ g, int ld,
                                       int row0, int k0, unsigned (*S)[36], int tid) {
    int r = tid >> 2;
    int c = (tid & 3) << 3;
    const float* p = g + (size_t)(row0 + r) * ld + k0 + c;
    #pragma unroll
    for (int i = 0; i < 2; i++) {
        float4 v = *(const float4*)(p + 4*i);
        uint4 u;
        u.x = f2tf(v.x); u.y = f2tf(v.y); u.z = f2tf(v.z); u.w = f2tf(v.w);
        *(uint4*)&S[r][c + 4*i] = u;
    }
}

// One BK=32 step of warp-level mma. Warp tile: 64 x (NT*8).
// acc[mt][nt][4]
template<int NT>
__device__ __forceinline__ void mma_block(const unsigned (*As)[36], const unsigned (*Bs)[36],
                                          int wm, int wn, int lane, float (*acc)[NT][4]) {
    #pragma unroll
    for (int ks = 0; ks < 4; ks++) {
        unsigned a[4][4];
        #pragma unroll
        for (int mt = 0; mt < 4; mt++) {
            int r = wm*64 + mt*16 + (lane >> 2);
            int c = ks*8 + (lane & 3);
            a[mt][0] = As[r][c];
            a[mt][1] = As[r+8][c];
            a[mt][2] = As[r][c+4];
            a[mt][3] = As[r+8][c+4];
        }
        unsigned b[NT][2];
        #pragma unroll
        for (int nt = 0; nt < NT; nt++) {
            int r = wn + nt*8 + (lane >> 2);
            int c = ks*8 + (lane & 3);
            b[nt][0] = Bs[r][c];
            b[nt][1] = Bs[r][c+4];
        }
        #pragma unroll
        for (int mt = 0; mt < 4; mt++)
            #pragma unroll
            for (int nt = 0; nt < NT; nt++)
                mma8(acc[mt][nt], a[mt][0], a[mt][1], a[mt][2], a[mt][3],
                     b[nt][0], b[nt][1]);
    }
}

// ---------------------------------------------------------------------------
// Projection: C[M=B*S, N=D] = X @ W^T; scatter to head layout (Q/K) or
// transposed head layout (V -> g_VT)
// ---------------------------------------------------------------------------
__global__ __launch_bounds__(256) void proj_kernel(
    const float* __restrict__ X, const float* __restrict__ W, int which)
{
    __shared__ unsigned As[128][36];
    __shared__ unsigned Bs[128][36];
    const int tid = threadIdx.x;
    const int lane = tid & 31;
    const int warp = tid >> 5;
    const int wm = warp & 1;
    const int wn = (warp >> 1) * 32;
    const int m0 = blockIdx.y * 128;
    const int n0 = blockIdx.x * 128;

    float acc[4][4][4];
    #pragma unroll
    for (int mt = 0; mt < 4; mt++)
        #pragma unroll
        for (int nt = 0; nt < 4; nt++)
            #pragma unroll
            for (int i = 0; i < 4; i++) acc[mt][nt][i] = 0.f;

    for (int k0 = 0; k0 < DD; k0 += 32) {
        load128(X, DD, m0, k0, As, tid);
        load128(W, DD, n0, k0, Bs, tid);
        __syncthreads();
        mma_block<4>(As, Bs, wm, wn, lane, acc);
        __syncthreads();
    }

    #pragma unroll
    for (int mt = 0; mt < 4; mt++) {
        int m_lo = m0 + wm*64 + mt*16 + (lane >> 2);
        int m_hi = m_lo + 8;
        int b_lo = m_lo >> 11, s_lo = m_lo & (SS-1);
        int b_hi = m_hi >> 11, s_hi = m_hi & (SS-1);
        #pragma unroll
        for (int nt = 0; nt < 4; nt++) {
            int cn = n0 + wn + nt*8 + 2*(lane & 3);
            int h = cn >> 6, d = cn & 63;
            float c0 = acc[mt][nt][0], c1 = acc[mt][nt][1];
            float c2 = acc[mt][nt][2], c3 = acc[mt][nt][3];
            if (which == 2) {
                float* base_d0 = g_VT + ((size_t)( (b_lo*HH + h)*DHH + d )) * SS;
                float* base_d1 = g_VT + ((size_t)( (b_lo*HH + h)*DHH + d+1 )) * SS;
                base_d0[s_lo] = c0;
                base_d1[s_lo] = c1;
                float* base2_d0 = g_VT + ((size_t)( (b_hi*HH + h)*DHH + d )) * SS;
                float* base2_d1 = g_VT + ((size_t)( (b_hi*HH + h)*DHH + d+1 )) * SS;
                base2_d0[s_hi] = c2;
                base2_d1[s_hi] = c3;
            } else {
                float* dst = (which == 0) ? g_QH : g_KH;
                float2 v0 = make_float2(c0, c1);
                float2 v1 = make_float2(c2, c3);
                *(float2*)&dst[ (((size_t)(b_lo*HH + h)*SS + s_lo) << 6) + d ] = v0;
                *(float2*)&dst[ (((size_t)(b_hi*HH + h)*SS + s_hi) << 6) + d ] = v1;
            }
        }
    }
}

// ---------------------------------------------------------------------------
// Scores: per (b,h): attn_raw = (QH @ KH^T)/8, masked
// ---------------------------------------------------------------------------
__global__ __launch_bounds__(256) void scores_kernel(
    const int* __restrict__ mask, float* __restrict__ attn)
{
    __shared__ unsigned As[128][36];
    __shared__ unsigned Bs[128][36];
    const int tid = threadIdx.x;
    const int lane = tid & 31;
    const int warp = tid >> 5;
    const int wm = warp & 1;
    const int wn = (warp >> 1) * 32;
    const int bh = blockIdx.z;
    const int m0 = blockIdx.y * 128;
    const int n0 = blockIdx.x * 128;
    const float* Q = g_QH + (size_t)bh * SS * DHH;
    const float* K = g_KH + (size_t)bh * SS * DHH;

    float acc[4][4][4];
    #pragma unroll
    for (int mt = 0; mt < 4; mt++)
        #pragma unroll
        for (int nt = 0; nt < 4; nt++)
            #pragma unroll
            for (int i = 0; i < 4; i++) acc[mt][nt][i] = 0.f;

    #pragma unroll
    for (int k0 = 0; k0 < DHH; k0 += 32) {
        load128(Q, DHH, m0, k0, As, tid);
        load128(K, DHH, n0, k0, Bs, tid);
        __syncthreads();
        mma_block<4>(As, Bs, wm, wn, lane, acc);
        __syncthreads();
    }

    float* Cp = attn + (size_t)bh * SS * SS;
    #pragma unroll
    for (int mt = 0; mt < 4; mt++) {
        int m_lo = m0 + wm*64 + mt*16 + (lane >> 2);
        int m_hi = m_lo + 8;
        #pragma unroll
        for (int nt = 0; nt < 4; nt++) {
            int cn = n0 + wn + nt*8 + 2*(lane & 3);
            int2 mm0 = *(const int2*)(mask + (size_t)m_lo * SS + cn);
            int2 mm1 = *(const int2*)(mask + (size_t)m_hi * SS + cn);
            float2 v0, v1;
            v0.x = mm0.x ? acc[mt][nt][0] * 0.125f : -1e34f;
            v0.y = mm0.y ? acc[mt][nt][1] * 0.125f : -1e34f;
            v1.x = mm1.x ? acc[mt][nt][2] * 0.125f : -1e34f;
            v1.y = mm1.y ? acc[mt][nt][3] * 0.125f : -1e34f;
            *(float2*)(Cp + (size_t)m_lo * SS + cn) = v0;
            *(float2*)(Cp + (size_t)m_hi * SS + cn) = v1;
        }
    }
}

// ---------------------------------------------------------------------------
// Row softmax in place: one block (256 thr) per row of 2048
// ---------------------------------------------------------------------------
__global__ __launch_bounds__(256) void softmax_kernel(float* __restrict__ attn)
{
    __shared__ float red[8];
    const size_t row = blockIdx.x;
    float* p = attn + row * SS;
    const int tid = threadIdx.x;

    float4 v0 = ((float4*)p)[tid];
    float4 v1 = ((float4*)p)[tid + 256];

    float m = fmaxf(fmaxf(fmaxf(v0.x, v0.y), fmaxf(v0.z, v0.w)),
                    fmaxf(fmaxf(v1.x, v1.y), fmaxf(v1.z, v1.w)));
    #pragma unroll
    for (int o = 16; o; o >>= 1) m = fmaxf(m, __shfl_xor_sync(0xffffffffu, m, o));
    if ((tid & 31) == 0) red[tid >> 5] = m;
    __syncthreads();
    if (tid == 0) {
        float mm = red[0];
        #pragma unroll
        for (int w = 1; w < 8; w++) mm = fmaxf(mm, red[w]);
        red[0] = mm;
    }
    __syncthreads();
    m = red[0];
    __syncthreads();

    v0.x = __expf(v0.x - m); v0.y = __expf(v0.y - m);
    v0.z = __expf(v0.z - m); v0.w = __expf(v0.w - m);
    v1.x = __expf(v1.x - m); v1.y = __expf(v1.y - m);
    v1.z = __expf(v1.z - m); v1.w = __expf(v1.w - m);

    float s = (v0.x + v0.y + v0.z + v0.w) + (v1.x + v1.y + v1.z + v1.w);
    #pragma unroll
    for (int o = 16; o; o >>= 1) s += __shfl_xor_sync(0xffffffffu, s, o);
    if ((tid & 31) == 0) red[tid >> 5] = s;
    __syncthreads();
    if (tid == 0) {
        float ss = red[0];
        #pragma unroll
        for (int w = 1; w < 8; w++) ss += red[w];
        red[0] = ss;
    }
    __syncthreads();
    s = red[0];

    float inv = 1.0f / s;
    v0.x *= inv; v0.y *= inv; v0.z *= inv; v0.w *= inv;
    v1.x *= inv; v1.y *= inv; v1.z *= inv; v1.w *= inv;
    ((float4*)p)[tid]       = v0;
    ((float4*)p)[tid + 256] = v1;
}

// ---------------------------------------------------------------------------
// PV: per (b,h): O = attn[S,S] @ VT[DH,S]^T -> g_O [B,S,D]
// BM=128, BN=64, BK=32
// ---------------------------------------------------------------------------
__global__ __launch_bounds__(256) void pv_kernel(const float* __restrict__ attn)
{
    __shared__ unsigned As[128][36];
    __shared__ unsigned Bs[64][36];
    const int tid = threadIdx.x;
    const int lane = tid & 31;
    const int warp = tid >> 5;
    const int wm = warp & 1;
    const int wn = (warp >> 1) * 16;
    const int bh = blockIdx.z;
    const int b = bh >> 4, h = bh & 15;
    const int m0 = blockIdx.x * 128;
    const float* P = attn + (size_t)bh * SS * SS;
    const float* VT = g_VT + (size_t)bh * DHH * SS;

    float acc[4][2][4];
    #pragma unroll
    for (int mt = 0; mt < 4; mt++)
        #pragma unroll
        for (int nt = 0; nt < 2; nt++)
            #pragma unroll
            for (int i = 0; i < 4; i++) acc[mt][nt][i] = 0.f;

    for (int k0 = 0; k0 < SS; k0 += 32) {
        load128(P, SS, m0, k0, As, tid);
        load64(VT, SS, 0, k0, Bs, tid);
        __syncthreads();
        mma_block<2>(As, Bs, wm, wn, lane, acc);
        __syncthreads();
    }

    #pragma unroll
    for (int mt = 0; mt < 4; mt++) {
        int s_lo = m0 + wm*64 + mt*16 + (lane >> 2);
        int s_hi = s_lo + 8;
        #pragma unroll
        for (int nt = 0; nt < 2; nt++) {
            int n = wn + nt*8 + 2*(lane & 3);
            float2 v0 = make_float2(acc[mt][nt][0], acc[mt][nt][1]);
            float2 v1 = make_float2(acc[mt][nt][2], acc[mt][nt][3]);
            *(float2*)&g_O[ ((size_t)(b*SS + s_lo))*DD + h*DHH + n ] = v0;
            *(float2*)&g_O[ ((size_t)(b*SS + s_hi))*DD + h*DHH + n ] = v1;
        }
    }
}

// ---------------------------------------------------------------------------
// Output: out = g_O @ Wo^T
// ---------------------------------------------------------------------------
__global__ __launch_bounds__(256) void out_kernel(
    const float* __restrict__ Wo, float* __restrict__ out)
{
    __shared__ unsigned As[128][36];
    __shared__ unsigned Bs[128][36];
    const int tid = threadIdx.x;
    const int lane = tid & 31;
    const int warp = tid >> 5;
    const int wm = warp & 1;
    const int wn = (warp >> 1) * 32;
    const int m0 = blockIdx.y * 128;
    const int n0 = blockIdx.x * 128;

    float acc[4][4][4];
    #pragma unroll
    for (int mt = 0; mt < 4; mt++)
        #pragma unroll
        for (int nt = 0; nt < 4; nt++)
            #pragma unroll
            for (int i = 0; i < 4; i++) acc[mt][nt][i] = 0.f;

    for (int k0 = 0; k0 < DD; k0 += 32) {
        load128(g_O, DD, m0, k0, As, tid);
        load128(Wo, DD, n0, k0, Bs, tid);
        __syncthreads();
        mma_block<4>(As, Bs, wm, wn, lane, acc);
        __syncthreads();
    }

    #pragma unroll
    for (int mt = 0; mt < 4; mt++) {
        int m_lo = m0 + wm*64 + mt*16 + (lane >> 2);
        int m_hi = m_lo + 8;
        #pragma unroll
        for (int nt = 0; nt < 4; nt++) {
            int cn = n0 + wn + nt*8 + 2*(lane & 3);
            float2 v0 = make_float2(acc[mt][nt][0], acc[mt][nt][1]);
            float2 v1 = make_float2(acc[mt][nt][2], acc[mt][nt][3]);
            *(float2*)(out + (size_t)m_lo * DD + cn) = v0;
            *(float2*)(out + (size_t)m_hi * DD + cn) = v1;
        }
    }
}

// ---------------------------------------------------------------------------
extern "C" void kernel_launch(void* const* d_in, const int* in_sizes, int n_in,
                              void* d_out, int out_size)
{
    const float* q    = (const float*)d_in[0];
    const float* k    = (const float*)d_in[1];
    const float* v    = (const float*)d_in[2];
    const int*   mask = (const int*)  d_in[3];
    const float* Wq   = (const float*)d_in[4];
    const float* Wk   = (const float*)d_in[5];
    const float* Wv   = (const float*)d_in[6];
    const float* Wo   = (const float*)d_in[7];

    float* out  = (float*)d_out;
    float* attn = out + (size_t)BB * SS * DD;   // out first, then attn

    dim3 blk(256);
    dim3 gp(DD / 128, (BB * SS) / 128);         // 8 x 32
    proj_kernel<<<gp, blk>>>(q, Wq, 0);
    proj_kernel<<<gp, blk>>>(k, Wk, 1);
    proj_kernel<<<gp, blk>>>(v, Wv, 2);

    dim3 gs(SS / 128, SS / 128, BB * HH);       // 16 x 16 x 32
    scores_kernel<<<gs, blk>>>(mask, attn);

    softmax_kernel<<<BB * HH * SS, blk>>>(attn);

    pv_kernel<<<dim3(SS / 128, 1, BB * HH), blk>>>(attn);

    out_kernel<<<gp, blk>>>(Wo, out);
}

// round 6
// speedup vs baseline: 1.7991x; 1.2031x over previous
#include <cuda_runtime.h>
#include <cstdint>

#define BB  2
#define SS  2048
#define DD  1024
#define HH  16
#define DHH 64

// Scratch (allocation-free rule: __device__ globals)
__device__ float g_QH[BB*HH*SS*DHH];   // [B,H,S,DH]
__device__ float g_KH[BB*HH*SS*DHH];   // [B,H,S,DH]
__device__ float g_VT[BB*HH*DHH*SS];   // [B,H,DH,S]  (transposed V for NT PV gemm)
__device__ float g_O [BB*SS*DD];       // [B,S,D]

// ---------------------------------------------------------------------------
// Smem: fragment-native SoA layout, double buffered. 48 KB exactly.
// A plane e: e=0:(r,k) e=1:(r+8,k) e=2:(r,k+4) e=3:(r+8,k+4)
//   value at [e][g][ks][lane] = A(16g + lane/4 + 8*(e&1), 8ks + lane%4 + 4*(e>>1))
// B plane e: e=0:(n,k) e=1:(n,k+4)
//   value at [e][g][ks][lane] = B(8g + lane/4, 8ks + lane%4 + 4e)
// ---------------------------------------------------------------------------
struct __align__(16) Smem {
    unsigned A[2][4][8][4][32];  // [buf][e][mgroup(16 rows)][ks][lane]  32 KB
    unsigned B[2][2][8][4][32];  // [buf][e][ngroup(8 cols)][ks][lane]   16 KB
};

__device__ __forceinline__ unsigned f2tf(float f) {
    unsigned u;
    asm("cvt.rna.tf32.f32 %0, %1;" : "=r"(u) : "f"(f));
    return u;
}

__device__ __forceinline__ void mma8(float c[4],
                                     unsigned a0, unsigned a1, unsigned a2, unsigned a3,
                                     unsigned b0, unsigned b1) {
    asm("mma.sync.aligned.m16n8k8.row.col.f32.tf32.tf32.f32 "
        "{%0,%1,%2,%3},{%4,%5,%6,%7},{%8,%9},{%0,%1,%2,%3};"
        : "+f"(c[0]), "+f"(c[1]), "+f"(c[2]), "+f"(c[3])
        : "r"(a0), "r"(a1), "r"(a2), "r"(a3), "r"(b0), "r"(b1));
}

// Store one thread's A float4s (row r, cols cbase+4i..+3) into fragment planes.
__device__ __forceinline__ void stsA(Smem& S, int buf, int r, int cbase, const float4* v) {
    const int g    = r >> 4;
    const int rr   = r & 15;
    const int Lb   = (rr & 7) * 4;
    const int erow = rr >> 3;
    #pragma unroll
    for (int i = 0; i < 4; i++) {
        const int c  = cbase + 4 * i;
        const int ks = c >> 3;
        const int e  = erow + ((c & 4) >> 1);    // +2 when k-half
        uint4 u;
        u.x = f2tf(v[i].x); u.y = f2tf(v[i].y); u.z = f2tf(v[i].z); u.w = f2tf(v[i].w);
        *(uint4*)&S.A[buf][e][g][ks][Lb] = u;    // 4 consecutive lanes
    }
}

__device__ __forceinline__ void stsB(Smem& S, int buf, int n, int cbase, const float4* v) {
    const int g  = n >> 3;
    const int Lb = (n & 7) * 4;
    #pragma unroll
    for (int i = 0; i < 2; i++) {
        const int c  = cbase + 4 * i;
        const int ks = c >> 3;
        const int e  = (c & 4) >> 2;
        uint4 u;
        u.x = f2tf(v[i].x); u.y = f2tf(v[i].y); u.z = f2tf(v[i].z); u.w = f2tf(v[i].w);
        *(uint4*)&S.B[buf][e][g][ks][Lb] = u;
    }
}

// One BK=32 step: warp tile 64 rows x 16 cols (mt=4, nt=2).
__device__ __forceinline__ void mma_step(const Smem& S, int buf, int lane, int wm, int wn,
                                         float (*acc)[2][4]) {
    #pragma unroll
    for (int ks = 0; ks < 4; ks++) {
        unsigned a[4][4];
        #pragma unroll
        for (int mt = 0; mt < 4; mt++) {
            const int g = wm * 4 + mt;
            a[mt][0] = S.A[buf][0][g][ks][lane];
            a[mt][1] = S.A[buf][1][g][ks][lane];
            a[mt][2] = S.A[buf][2][g][ks][lane];
            a[mt][3] = S.A[buf][3][g][ks][lane];
        }
        unsigned b[2][2];
        #pragma unroll
        for (int nt = 0; nt < 2; nt++) {
            const int g = wn * 2 + nt;
            b[nt][0] = S.B[buf][0][g][ks][lane];
            b[nt][1] = S.B[buf][1][g][ks][lane];
        }
        #pragma unroll
        for (int mt = 0; mt < 4; mt++)
            #pragma unroll
            for (int nt = 0; nt < 2; nt++)
                mma8(acc[mt][nt], a[mt][0], a[mt][1], a[mt][2], a[mt][3],
                     b[nt][0], b[nt][1]);
    }
}

// NT GEMM core: C[128 x 64] += A[128,K] @ B[64,K]^T, K = KB*32.
// Double-buffered smem, register prefetch of the next gmem tile.
template<int KB>
__device__ __forceinline__ void gemm_core(
    const float* __restrict__ Ag, int lda,
    const float* __restrict__ Bg, int ldb,
    Smem& S, float (*acc)[2][4])
{
    const int tid  = threadIdx.x;
    const int lane = tid & 31;
    const int warp = tid >> 5;
    const int wm = warp & 1;
    const int wn = warp >> 1;

    const int ar = tid >> 1, ac = (tid & 1) << 4;   // A: 128 rows, 2 thr/row
    const int br = tid >> 2, bc = (tid & 3) << 3;   // B: 64 rows, 4 thr/row
    const float* Ap = Ag + (size_t)ar * lda + ac;
    const float* Bp = Bg + (size_t)br * ldb + bc;

    float4 aL[4], bL[2];
    #pragma unroll
    for (int i = 0; i < 4; i++) aL[i] = *(const float4*)(Ap + 4 * i);
    #pragma unroll
    for (int i = 0; i < 2; i++) bL[i] = *(const float4*)(Bp + 4 * i);
    stsA(S, 0, ar, ac, aL);
    stsB(S, 0, br, bc, bL);
    __syncthreads();

    #pragma unroll 2
    for (int kb = 1; kb < KB; kb++) {
        #pragma unroll
        for (int i = 0; i < 4; i++) aL[i] = *(const float4*)(Ap + kb * 32 + 4 * i);
        #pragma unroll
        for (int i = 0; i < 2; i++) bL[i] = *(const float4*)(Bp + kb * 32 + 4 * i);
        mma_step(S, (kb - 1) & 1, lane, wm, wn, acc);
        stsA(S, kb & 1, ar, ac, aL);
        stsB(S, kb & 1, br, bc, bL);
        __syncthreads();
    }
    mma_step(S, (KB - 1) & 1, lane, wm, wn, acc);
}

// ---------------------------------------------------------------------------
// Projection: C[M=B*S, N=D] = X @ W^T; scatter to head layout (Q/K) or
// transposed head layout (V -> g_VT).  BM=128, BN=64.
// ---------------------------------------------------------------------------
__global__ __launch_bounds__(256, 2) void proj_kernel(
    const float* __restrict__ X, const float* __restrict__ W, int which)
{
    __shared__ Smem S;
    const int m0 = blockIdx.y * 128;
    const int n0 = blockIdx.x * 64;
    float acc[4][2][4] = {};
    gemm_core<DD/32>(X + (size_t)m0 * DD, DD, W + (size_t)n0 * DD, DD, S, acc);

    const int tid = threadIdx.x, lane = tid & 31, warp = tid >> 5;
    const int wm = warp & 1, wn = warp >> 1;
    #pragma unroll
    for (int mt = 0; mt < 4; mt++) {
        int m_lo = m0 + wm * 64 + mt * 16 + (lane >> 2);
        int m_hi = m_lo + 8;
        int b_lo = m_lo >> 11, s_lo = m_lo & (SS - 1);
        int b_hi = m_hi >> 11, s_hi = m_hi & (SS - 1);
        #pragma unroll
        for (int nt = 0; nt < 2; nt++) {
            int cn = n0 + wn * 16 + nt * 8 + 2 * (lane & 3);
            int h = cn >> 6, d = cn & 63;
            float c0 = acc[mt][nt][0], c1 = acc[mt][nt][1];
            float c2 = acc[mt][nt][2], c3 = acc[mt][nt][3];
            if (which == 2) {
                g_VT[((size_t)((b_lo*HH + h)*DHH + d    )) * SS + s_lo] = c0;
                g_VT[((size_t)((b_lo*HH + h)*DHH + d + 1)) * SS + s_lo] = c1;
                g_VT[((size_t)((b_hi*HH + h)*DHH + d    )) * SS + s_hi] = c2;
                g_VT[((size_t)((b_hi*HH + h)*DHH + d + 1)) * SS + s_hi] = c3;
            } else {
                float* dst = (which == 0) ? g_QH : g_KH;
                *(float2*)&dst[(((size_t)(b_lo*HH + h)*SS + s_lo) << 6) + d] = make_float2(c0, c1);
                *(float2*)&dst[(((size_t)(b_hi*HH + h)*SS + s_hi) << 6) + d] = make_float2(c2, c3);
            }
        }
    }
}

// ---------------------------------------------------------------------------
// Scores: per (b,h): attn_raw = (QH @ KH^T)/8, masked.  BM=128, BN=64, K=64.
// ---------------------------------------------------------------------------
__global__ __launch_bounds__(256, 2) void scores_kernel(
    const int* __restrict__ mask, float* __restrict__ attn)
{
    __shared__ Smem S;
    const int bh = blockIdx.z;
    const int m0 = blockIdx.y * 128;
    const int n0 = blockIdx.x * 64;
    float acc[4][2][4] = {};
    gemm_core<DHH/32>(g_QH + (size_t)bh * SS * DHH + (size_t)m0 * DHH, DHH,
                      g_KH + (size_t)bh * SS * DHH + (size_t)n0 * DHH, DHH, S, acc);

    const int tid = threadIdx.x, lane = tid & 31, warp = tid >> 5;
    const int wm = warp & 1, wn = warp >> 1;
    float* Cp = attn + (size_t)bh * SS * SS;
    #pragma unroll
    for (int mt = 0; mt < 4; mt++) {
        int m_lo = m0 + wm * 64 + mt * 16 + (lane >> 2);
        int m_hi = m_lo + 8;
        #pragma unroll
        for (int nt = 0; nt < 2; nt++) {
            int cn = n0 + wn * 16 + nt * 8 + 2 * (lane & 3);
            int2 mm0 = *(const int2*)(mask + (size_t)m_lo * SS + cn);
            int2 mm1 = *(const int2*)(mask + (size_t)m_hi * SS + cn);
            float2 v0, v1;
            v0.x = mm0.x ? acc[mt][nt][0] * 0.125f : -1e34f;
            v0.y = mm0.y ? acc[mt][nt][1] * 0.125f : -1e34f;
            v1.x = mm1.x ? acc[mt][nt][2] * 0.125f : -1e34f;
            v1.y = mm1.y ? acc[mt][nt][3] * 0.125f : -1e34f;
            *(float2*)(Cp + (size_t)m_lo * SS + cn) = v0;
            *(float2*)(Cp + (size_t)m_hi * SS + cn) = v1;
        }
    }
}

// ---------------------------------------------------------------------------
// Row softmax in place: one block (256 thr) per row of 2048
// ---------------------------------------------------------------------------
__global__ __launch_bounds__(256) void softmax_kernel(float* __restrict__ attn)
{
    __shared__ float red[8];
    const size_t row = blockIdx.x;
    float* p = attn + row * SS;
    const int tid = threadIdx.x;

    float4 v0 = ((float4*)p)[tid];
    float4 v1 = ((float4*)p)[tid + 256];

    float m = fmaxf(fmaxf(fmaxf(v0.x, v0.y), fmaxf(v0.z, v0.w)),
                    fmaxf(fmaxf(v1.x, v1.y), fmaxf(v1.z, v1.w)));
    #pragma unroll
    for (int o = 16; o; o >>= 1) m = fmaxf(m, __shfl_xor_sync(0xffffffffu, m, o));
    if ((tid & 31) == 0) red[tid >> 5] = m;
    __syncthreads();
    if (tid == 0) {
        float mm = red[0];
        #pragma unroll
        for (int w = 1; w < 8; w++) mm = fmaxf(mm, red[w]);
        red[0] = mm;
    }
    __syncthreads();
    m = red[0];
    __syncthreads();

    v0.x = __expf(v0.x - m); v0.y = __expf(v0.y - m);
    v0.z = __expf(v0.z - m); v0.w = __expf(v0.w - m);
    v1.x = __expf(v1.x - m); v1.y = __expf(v1.y - m);
    v1.z = __expf(v1.z - m); v1.w = __expf(v1.w - m);

    float s = (v0.x + v0.y + v0.z + v0.w) + (v1.x + v1.y + v1.z + v1.w);
    #pragma unroll
    for (int o = 16; o; o >>= 1) s += __shfl_xor_sync(0xffffffffu, s, o);
    if ((tid & 31) == 0) red[tid >> 5] = s;
    __syncthreads();
    if (tid == 0) {
        float ss = red[0];
        #pragma unroll
        for (int w = 1; w < 8; w++) ss += red[w];
        red[0] = ss;
    }
    __syncthreads();
    s = red[0];

    float inv = 1.0f / s;
    v0.x *= inv; v0.y *= inv; v0.z *= inv; v0.w *= inv;
    v1.x *= inv; v1.y *= inv; v1.z *= inv; v1.w *= inv;
    ((float4*)p)[tid]       = v0;
    ((float4*)p)[tid + 256] = v1;
}

// ---------------------------------------------------------------------------
// PV: per (b,h): O = attn[S,S] @ VT[DH,S]^T -> g_O [B,S,D].  BM=128, BN=64.
// ---------------------------------------------------------------------------
__global__ __launch_bounds__(256, 2) void pv_kernel(const float* __restrict__ attn)
{
    __shared__ Smem S;
    const int bh = blockIdx.z;
    const int b = bh >> 4, h = bh & 15;
    const int m0 = blockIdx.x * 128;
    float acc[4][2][4] = {};
    gemm_core<SS/32>(attn + (size_t)bh * SS * SS + (size_t)m0 * SS, SS,
                     g_VT + (size_t)bh * DHH * SS, SS, S, acc);

    const int tid = threadIdx.x, lane = tid & 31, warp = tid >> 5;
    const int wm = warp & 1, wn = warp >> 1;
    #pragma unroll
    for (int mt = 0; mt < 4; mt++) {
        int s_lo = m0 + wm * 64 + mt * 16 + (lane >> 2);
        int s_hi = s_lo + 8;
        #pragma unroll
        for (int nt = 0; nt < 2; nt++) {
            int n = wn * 16 + nt * 8 + 2 * (lane & 3);
            *(float2*)&g_O[((size_t)(b*SS + s_lo)) * DD + h*DHH + n] =
                make_float2(acc[mt][nt][0], acc[mt][nt][1]);
            *(float2*)&g_O[((size_t)(b*SS + s_hi)) * DD + h*DHH + n] =
                make_float2(acc[mt][nt][2], acc[mt][nt][3]);
        }
    }
}

// ---------------------------------------------------------------------------
// Output: out = g_O @ Wo^T.  BM=128, BN=64.
// ---------------------------------------------------------------------------
__global__ __launch_bounds__(256, 2) void out_kernel(
    const float* __restrict__ Wo, float* __restrict__ out)
{
    __shared__ Smem S;
    const int m0 = blockIdx.y * 128;
    const int n0 = blockIdx.x * 64;
    float acc[4][2][4] = {};
    gemm_core<DD/32>(g_O + (size_t)m0 * DD, DD, Wo + (size_t)n0 * DD, DD, S, acc);

    const int tid = threadIdx.x, lane = tid & 31, warp = tid >> 5;
    const int wm = warp & 1, wn = warp >> 1;
    #pragma unroll
    for (int mt = 0; mt < 4; mt++) {
        int m_lo = m0 + wm * 64 + mt * 16 + (lane >> 2);
        int m_hi = m_lo + 8;
        #pragma unroll
        for (int nt = 0; nt < 2; nt++) {
            int cn = n0 + wn * 16 + nt * 8 + 2 * (lane & 3);
            *(float2*)(out + (size_t)m_lo * DD + cn) =
                make_float2(acc[mt][nt][0], acc[mt][nt][1]);
            *(float2*)(out + (size_t)m_hi * DD + cn) =
                make_float2(acc[mt][nt][2], acc[mt][nt][3]);
        }
    }
}

// ---------------------------------------------------------------------------
extern "C" void kernel_launch(void* const* d_in, const int* in_sizes, int n_in,
                              void* d_out, int out_size)
{
    const float* q    = (const float*)d_in[0];
    const float* k    = (const float*)d_in[1];
    const float* v    = (const float*)d_in[2];
    const int*   mask = (const int*)  d_in[3];
    const float* Wq   = (const float*)d_in[4];
    const float* Wk   = (const float*)d_in[5];
    const float* Wv   = (const float*)d_in[6];
    const float* Wo   = (const float*)d_in[7];

    float* out  = (float*)d_out;
    float* attn = out + (size_t)BB * SS * DD;   // out first, then attn

    dim3 blk(256);
    dim3 gp(DD / 64, (BB * SS) / 128);          // 16 x 32
    proj_kernel<<<gp, blk>>>(q, Wq, 0);
    proj_kernel<<<gp, blk>>>(k, Wk, 1);
    proj_kernel<<<gp, blk>>>(v, Wv, 2);

    dim3 gs(SS / 64, SS / 128, BB * HH);        // 32 x 16 x 32
    scores_kernel<<<gs, blk>>>(mask, attn);

    softmax_kernel<<<BB * HH * SS, blk>>>(attn);

    pv_kernel<<<dim3(SS / 128, 1, BB * HH), blk>>>(attn);

    out_kernel<<<gp, blk>>>(Wo, out);
}